// round 2
// baseline (speedup 1.0000x reference)
#include <cuda_runtime.h>
#include <cstdint>

// ---------------- problem dims ----------------
constexpr int Bc   = 128;     // batch
constexpr int Nf   = 196;     // spatial features
constexpr int ENC  = 512;
constexpr int AD   = 512;     // attention dim
constexpr int DD   = 512;     // decoder dim
constexpr int ED   = 300;     // embed dim
constexpr int VV   = 10000;   // vocab
constexpr int LL   = 25;
constexpr int TT   = 24;      // L-1
constexpr int KCAT = ED + ENC + DD;   // 1324
constexpr int G4   = 4 * DD;          // 2048

// ---------------- device scratch (static; no runtime alloc) ----------------
__device__ float g_featproj[Bc * Nf * AD];       // 51.4 MB
__device__ float g_Wcat[KCAT * G4];              // 10.9 MB
__device__ float g_bcat[G4];
__device__ float g_meanf[Bc * ENC];
__device__ float g_h[Bc * DD];
__device__ float g_c[Bc * DD];
__device__ float g_decproj[Bc * AD];
__device__ float g_scores[Bc * Nf];
__device__ float g_alpha[Bc * Nf];
__device__ float g_context[Bc * ENC];
__device__ float g_xcat[Bc * KCAT];
__device__ float g_gates[Bc * G4];
__device__ float g_Hall[TT * Bc * DD];           // 6.3 MB

// ---------------- generic tiled fp32 GEMM: C = A[M,K] @ B[K,N] + bias[n] ----------------
// MODE 0: C[m*N+n]   MODE 1: m = t*128+b ; C[(b*TT+t)*N + n]  (preds remap)
template<int BM, int BN, int BK, int TM, int TN, int MODE>
__global__ void gemm_bias(const float* __restrict__ A, const float* __restrict__ Bm,
                          const float* __restrict__ bias, float* __restrict__ C,
                          int M, int N, int K)
{
    constexpr int THREADS = (BM / TM) * (BN / TN);
    __shared__ float As[BK][BM];
    __shared__ float Bs[BK][BN];

    const int tid   = threadIdx.x;
    const int tcols = BN / TN;
    const int tx    = tid % tcols;
    const int ty    = tid / tcols;
    const int row0  = blockIdx.y * BM;
    const int col0  = blockIdx.x * BN;

    float acc[TM][TN];
#pragma unroll
    for (int i = 0; i < TM; i++)
#pragma unroll
        for (int j = 0; j < TN; j++) acc[i][j] = 0.f;

    constexpr int A_F4 = BM * BK / 4;
    constexpr int B_F4 = BK * BN / 4;
    constexpr int AKQ  = BK / 4;
    constexpr int BNQ  = BN / 4;

    for (int k0 = 0; k0 < K; k0 += BK) {
        // A tile -> As[k][m] (transposed)
#pragma unroll
        for (int l = tid; l < A_F4; l += THREADS) {
            int m  = l / AKQ;
            int kq = (l % AKQ) * 4;
            int gm = row0 + m;
            int gk = k0 + kq;
            float4 v = make_float4(0.f, 0.f, 0.f, 0.f);
            if (gm < M && gk < K)
                v = *reinterpret_cast<const float4*>(A + (size_t)gm * K + gk);
            As[kq + 0][m] = v.x; As[kq + 1][m] = v.y;
            As[kq + 2][m] = v.z; As[kq + 3][m] = v.w;
        }
        // B tile -> Bs[k][n]
#pragma unroll
        for (int l = tid; l < B_F4; l += THREADS) {
            int k  = l / BNQ;
            int nq = (l % BNQ) * 4;
            int gk = k0 + k;
            int gn = col0 + nq;
            float4 v = make_float4(0.f, 0.f, 0.f, 0.f);
            if (gk < K && gn < N)
                v = *reinterpret_cast<const float4*>(Bm + (size_t)gk * N + gn);
            *reinterpret_cast<float4*>(&Bs[k][nq]) = v;
        }
        __syncthreads();
#pragma unroll
        for (int kk = 0; kk < BK; kk++) {
            float ra[TM], rb[TN];
#pragma unroll
            for (int i = 0; i < TM; i++) ra[i] = As[kk][ty * TM + i];
#pragma unroll
            for (int j = 0; j < TN; j++) rb[j] = Bs[kk][tx * TN + j];
#pragma unroll
            for (int i = 0; i < TM; i++)
#pragma unroll
                for (int j = 0; j < TN; j++)
                    acc[i][j] = fmaf(ra[i], rb[j], acc[i][j]);
        }
        __syncthreads();
    }

#pragma unroll
    for (int i = 0; i < TM; i++) {
        int m = row0 + ty * TM + i;
        if (m >= M) continue;
#pragma unroll
        for (int j = 0; j < TN; j++) {
            int n = col0 + tx * TN + j;
            if (n >= N) continue;
            float v = acc[i][j] + bias[n];
            if (MODE == 0) {
                C[(size_t)m * N + n] = v;
            } else {
                int t = m >> 7;          // m = t*128 + b
                int b = m & 127;
                C[(size_t)(b * TT + t) * N + n] = v;
            }
        }
    }
}

// ---------------- setup kernels ----------------
__global__ void wcat_kernel(const float* __restrict__ Wih, const float* __restrict__ Whh,
                            const float* __restrict__ bih, const float* __restrict__ bhh)
{
    int idx = blockIdx.x * blockDim.x + threadIdx.x;
    const int n_ih = (ED + ENC) * G4;          // 812*2048
    const int total = KCAT * G4;
    if (idx < n_ih)          g_Wcat[idx] = Wih[idx];
    else if (idx < total)    g_Wcat[idx] = Whh[idx - n_ih];
    if (idx < G4)            g_bcat[idx] = bih[idx] + bhh[idx];
}

__global__ void meanf_kernel(const float* __restrict__ feat)
{
    int idx = blockIdx.x * blockDim.x + threadIdx.x;
    if (idx >= Bc * ENC) return;
    int b = idx >> 9;          // /512
    int d = idx & 511;
    const float* p = feat + (size_t)b * Nf * ENC + d;
    float s = 0.f;
#pragma unroll 4
    for (int n = 0; n < Nf; n++) s += p[(size_t)n * ENC];
    g_meanf[idx] = s * (1.f / (float)Nf);
}

// ---------------- per-step kernels ----------------
__global__ void scores_kernel(const float* __restrict__ w_att, const float* __restrict__ b_att)
{
    int gtid = blockIdx.x * blockDim.x + threadIdx.x;
    int warp = gtid >> 5;
    int lane = gtid & 31;
    if (warp >= Bc * Nf) return;
    int b = warp / Nf;
    const float* fpr = g_featproj + (size_t)warp * AD;
    const float* dpr = g_decproj + (size_t)b * AD;
    float s = 0.f;
#pragma unroll 4
    for (int a = lane; a < AD; a += 32)
        s += tanhf(fpr[a] + dpr[a]) * w_att[a];
#pragma unroll
    for (int o = 16; o; o >>= 1) s += __shfl_xor_sync(0xFFFFFFFFu, s, o);
    if (lane == 0) g_scores[warp] = s + b_att[0];
}

__global__ void softmax_kernel(float* __restrict__ alpha_out, int t)
{
    int b = blockIdx.x;
    int tid = threadIdx.x;               // 256 threads
    __shared__ float sh[256];
    float v = (tid < Nf) ? g_scores[b * Nf + tid] : -1e30f;
    sh[tid] = v; __syncthreads();
    for (int s = 128; s; s >>= 1) { if (tid < s) sh[tid] = fmaxf(sh[tid], sh[tid + s]); __syncthreads(); }
    float m = sh[0]; __syncthreads();
    float e = (tid < Nf) ? expf(v - m) : 0.f;
    sh[tid] = e; __syncthreads();
    for (int s = 128; s; s >>= 1) { if (tid < s) sh[tid] += sh[tid + s]; __syncthreads(); }
    float inv = 1.f / sh[0];
    if (tid < Nf) {
        float a = e * inv;
        g_alpha[b * Nf + tid] = a;
        if (alpha_out) alpha_out[(size_t)(b * TT + t) * Nf + tid] = a;
    }
}

__global__ void context_kernel(const float* __restrict__ feat)
{
    int b = blockIdx.x;
    int tid = threadIdx.x;               // 512 threads, one per d
    __shared__ float al[Nf];
    if (tid < Nf) al[tid] = g_alpha[b * Nf + tid];
    __syncthreads();
    const float* fb = feat + (size_t)b * Nf * ENC;
    float s = 0.f;
#pragma unroll 4
    for (int n = 0; n < Nf; n++) s += al[n] * fb[(size_t)n * ENC + tid];
    g_context[b * ENC + tid] = s;
}

__global__ void xcat_kernel(const int* __restrict__ captions, const float* __restrict__ emb, int t)
{
    int idx = blockIdx.x * blockDim.x + threadIdx.x;
    if (idx >= Bc * KCAT) return;
    int b = idx / KCAT;
    int j = idx - b * KCAT;
    float v;
    if (j < ED) {
        int tok = captions[b * LL + t];
        v = emb[(size_t)tok * ED + j];
    } else if (j < ED + ENC) {
        v = g_context[b * ENC + (j - ED)];
    } else {
        v = g_h[b * DD + (j - ED - ENC)];
    }
    g_xcat[idx] = v;
}

__global__ void lstm_kernel(int t)
{
    int idx = blockIdx.x * blockDim.x + threadIdx.x;
    if (idx >= Bc * DD) return;
    int b = idx >> 9;
    int d = idx & 511;
    const float* g = g_gates + (size_t)b * G4;
    float gi = g[d];
    float gf = g[DD + d];
    float gg = g[2 * DD + d];
    float go = g[3 * DD + d];
    float si = 1.f / (1.f + expf(-gi));
    float sf = 1.f / (1.f + expf(-gf));
    float so = 1.f / (1.f + expf(-go));
    float cn = sf * g_c[idx] + si * tanhf(gg);
    float hn = so * tanhf(cn);
    g_c[idx] = cn;
    g_h[idx] = hn;
    g_Hall[(size_t)t * Bc * DD + idx] = hn;
}

// ---------------- host launcher ----------------
extern "C" void kernel_launch(void* const* d_in, const int* in_sizes, int n_in,
                              void* d_out, int out_size)
{
    const float* features = (const float*)d_in[0];
    const int*   captions = (const int*)  d_in[1];
    const float* embedding= (const float*)d_in[2];
    const float* W_enc    = (const float*)d_in[3];
    const float* b_enc    = (const float*)d_in[4];
    const float* W_dec    = (const float*)d_in[5];
    const float* b_dec    = (const float*)d_in[6];
    const float* w_att    = (const float*)d_in[7];
    const float* b_att    = (const float*)d_in[8];
    const float* Wi_h     = (const float*)d_in[9];
    const float* bi_h     = (const float*)d_in[10];
    const float* Wi_c     = (const float*)d_in[11];
    const float* bi_c     = (const float*)d_in[12];
    const float* W_ih     = (const float*)d_in[13];
    const float* b_ih     = (const float*)d_in[14];
    const float* W_hh     = (const float*)d_in[15];
    const float* b_hh     = (const float*)d_in[16];
    const float* W_out    = (const float*)d_in[17];
    const float* b_out    = (const float*)d_in[18];

    float* out = (float*)d_out;
    const size_t PRED_SZ = (size_t)Bc * TT * VV;
    float* alpha_out = ((size_t)out_size >= PRED_SZ + (size_t)Bc * TT * Nf)
                           ? (out + PRED_SZ) : nullptr;

    static float *p_featproj = nullptr, *p_Wcat, *p_bcat, *p_meanf, *p_h, *p_c,
                 *p_decproj, *p_xcat, *p_gates, *p_Hall;
    if (!p_featproj) {
        cudaGetSymbolAddress((void**)&p_featproj, g_featproj);
        cudaGetSymbolAddress((void**)&p_Wcat,     g_Wcat);
        cudaGetSymbolAddress((void**)&p_bcat,     g_bcat);
        cudaGetSymbolAddress((void**)&p_meanf,    g_meanf);
        cudaGetSymbolAddress((void**)&p_h,        g_h);
        cudaGetSymbolAddress((void**)&p_c,        g_c);
        cudaGetSymbolAddress((void**)&p_decproj,  g_decproj);
        cudaGetSymbolAddress((void**)&p_xcat,     g_xcat);
        cudaGetSymbolAddress((void**)&p_gates,    g_gates);
        cudaGetSymbolAddress((void**)&p_Hall,     g_Hall);
    }

    // ---- setup ----
    {
        int total = KCAT * G4;
        wcat_kernel<<<(total + 255) / 256, 256>>>(W_ih, W_hh, b_ih, b_hh);
    }
    meanf_kernel<<<(Bc * ENC + 255) / 256, 256>>>(features);

    // h0 = meanf @ Wi_h + bi_h ; c0 = meanf @ Wi_c + bi_c   (small GEMM 32x64 tiles)
    {
        dim3 grid((DD + 63) / 64, (Bc + 31) / 32);
        gemm_bias<32, 64, 16, 2, 4, 0><<<grid, 256>>>(p_meanf, Wi_h, bi_h, p_h, Bc, DD, ENC);
        gemm_bias<32, 64, 16, 2, 4, 0><<<grid, 256>>>(p_meanf, Wi_c, bi_c, p_c, Bc, DD, ENC);
    }

    // feat_proj = features @ W_enc + b_enc  (big GEMM)
    {
        dim3 grid((AD + 127) / 128, (Bc * Nf + 127) / 128);   // (4, 196)
        gemm_bias<128, 128, 16, 8, 8, 0><<<grid, 256>>>(features, W_enc, b_enc,
                                                        p_featproj, Bc * Nf, AD, ENC);
    }

    // ---- serial step loop ----
    for (int t = 0; t < TT; t++) {
        // dec_proj = h @ W_dec + b_dec
        {
            dim3 grid((AD + 63) / 64, (Bc + 31) / 32);
            gemm_bias<32, 64, 16, 2, 4, 0><<<grid, 256>>>(p_h, W_dec, b_dec, p_decproj, Bc, AD, DD);
        }
        // attention scores
        {
            int warps = Bc * Nf;
            scores_kernel<<<(warps * 32 + 255) / 256, 256>>>(w_att, b_att);
        }
        softmax_kernel<<<Bc, 256>>>(alpha_out, t);
        context_kernel<<<Bc, 512>>>(features);
        xcat_kernel<<<(Bc * KCAT + 255) / 256, 256>>>(captions, embedding, t);
        // gates = xcat @ Wcat + bcat
        {
            dim3 grid((G4 + 63) / 64, (Bc + 31) / 32);        // (32, 4)
            gemm_bias<32, 64, 16, 2, 4, 0><<<grid, 256>>>(p_xcat, p_Wcat, p_bcat,
                                                          p_gates, Bc, G4, KCAT);
        }
        lstm_kernel<<<(Bc * DD + 255) / 256, 256>>>(t);
    }

    // ---- final: preds = H_all @ W_out + b_out, remapped to [B,T,V] ----
    {
        dim3 grid((VV + 127) / 128, (TT * Bc + 127) / 128);   // (79, 24)
        gemm_bias<128, 128, 16, 8, 8, 1><<<grid, 256>>>(p_Hall, W_out, b_out,
                                                        out, TT * Bc, VV, DD);
    }
}

// round 3
// speedup vs baseline: 1.6641x; 1.6641x over previous
#include <cuda_runtime.h>
#include <cstdint>

// ---------------- problem dims ----------------
constexpr int Bc   = 128;     // batch
constexpr int Nf   = 196;     // spatial features
constexpr int ENC  = 512;
constexpr int AD   = 512;     // attention dim
constexpr int DD   = 512;     // decoder dim
constexpr int ED   = 300;     // embed dim
constexpr int VV   = 10000;   // vocab
constexpr int LL   = 25;
constexpr int TT   = 24;      // L-1
constexpr int KCAT = ED + ENC + DD;   // 1324
constexpr int G4   = 4 * DD;          // 2048
constexpr int KS   = 8;               // split-K factor for gates GEMM
constexpr int KCHUNK = 168;           // ceil(1324/8) rounded to mult of 8

// ---------------- device scratch (static; no runtime alloc) ----------------
__device__ float g_featproj[Bc * Nf * AD];        // 51.4 MB
__device__ float g_Wcat[KCAT * G4];               // 10.9 MB (gate-interleaved: col = 4d+g)
__device__ float g_bcat[G4];
__device__ float g_meanf[Bc * ENC];
__device__ float g_c[Bc * DD];
__device__ float g_decproj[Bc * AD];
__device__ float g_xcat[TT * Bc * KCAT];          // 16.3 MB  [t][b][emb|ctx|h]
__device__ float g_gpart[KS * Bc * G4];           // 8 MB split-K partials
__device__ float g_Hall[TT * Bc * DD];            // 6.3 MB

// ================= TF32 tensor-core GEMM: C = A[M,K]@B[K,N] + bias =================
// BM=BN=128, BK=32, 256 threads (8 warps as 2x4, warp tile 64x32), m16n8k8 tf32.
// mode 0: C[m*ldc+n].  mode 1: m = t*128+b -> C[(b*TT+t)*ldc + n] (preds remap).
// Requires M%128==0, K%32==0, lda%4==0, ldb%4==0, N%4==0. N-edge guarded.
__device__ __forceinline__ uint32_t f2tf(float x) {
    uint32_t r; asm("cvt.rna.tf32.f32 %0, %1;" : "=r"(r) : "f"(x)); return r;
}
__device__ __forceinline__ void mma8(float* c, const uint32_t* a, const uint32_t* b) {
    asm volatile("mma.sync.aligned.m16n8k8.row.col.f32.tf32.tf32.f32 "
                 "{%0,%1,%2,%3},{%4,%5,%6,%7},{%8,%9},{%0,%1,%2,%3};"
                 : "+f"(c[0]), "+f"(c[1]), "+f"(c[2]), "+f"(c[3])
                 : "r"(a[0]), "r"(a[1]), "r"(a[2]), "r"(a[3]), "r"(b[0]), "r"(b[1]));
}

__global__ __launch_bounds__(256)
void gemm_tf32(const float* __restrict__ A, int lda,
               const float* __restrict__ B, int ldb,
               const float* __restrict__ bias, float* __restrict__ C, int ldc,
               int M, int N, int K, int mode)
{
    constexpr int ASTR = 36;    // As row stride (floats) -> conflict-free frag loads
    constexpr int BSTR = 136;   // Bs row stride
    __shared__ float As[128 * ASTR];   // [m][k]
    __shared__ float Bs[32 * BSTR];    // [k][n]

    const int tid  = threadIdx.x;
    const int lane = tid & 31, warp = tid >> 5;
    const int wm = (warp >> 2) * 64;      // warp row offset
    const int wn = (warp & 3) * 32;       // warp col offset
    const int l4 = lane >> 2, lq = lane & 3;
    const int row0 = blockIdx.y * 128;
    const int col0 = blockIdx.x * 128;

    float acc[4][4][4];
#pragma unroll
    for (int i = 0; i < 4; i++)
#pragma unroll
        for (int j = 0; j < 4; j++) {
            acc[i][j][0] = 0.f; acc[i][j][1] = 0.f; acc[i][j][2] = 0.f; acc[i][j][3] = 0.f;
        }

    const uint32_t* Asu = reinterpret_cast<const uint32_t*>(As);
    const uint32_t* Bsu = reinterpret_cast<const uint32_t*>(Bs);

    for (int k0 = 0; k0 < K; k0 += 32) {
        // A tile: 128x32 = 1024 float4 slots
#pragma unroll
        for (int i = 0; i < 4; i++) {
            int l = tid + i * 256;
            int m = l >> 3, kq = (l & 7) << 2;
            float4 v = *reinterpret_cast<const float4*>(A + (size_t)(row0 + m) * lda + k0 + kq);
            uint4 u = make_uint4(f2tf(v.x), f2tf(v.y), f2tf(v.z), f2tf(v.w));
            *reinterpret_cast<uint4*>(As + m * ASTR + kq) = u;
        }
        // B tile: 32x128 = 1024 float4 slots
#pragma unroll
        for (int i = 0; i < 4; i++) {
            int l = tid + i * 256;
            int k = l >> 5, nq = (l & 31) << 2;
            int gn = col0 + nq;
            float4 v = make_float4(0.f, 0.f, 0.f, 0.f);
            if (gn < N)
                v = *reinterpret_cast<const float4*>(B + (size_t)(k0 + k) * ldb + gn);
            uint4 u = make_uint4(f2tf(v.x), f2tf(v.y), f2tf(v.z), f2tf(v.w));
            *reinterpret_cast<uint4*>(Bs + k * BSTR + nq) = u;
        }
        __syncthreads();
#pragma unroll
        for (int kk = 0; kk < 32; kk += 8) {
            uint32_t af[4][4], bf[4][2];
#pragma unroll
            for (int mi = 0; mi < 4; mi++) {
                int r = wm + 16 * mi + l4;
                af[mi][0] = Asu[r * ASTR + kk + lq];
                af[mi][1] = Asu[(r + 8) * ASTR + kk + lq];
                af[mi][2] = Asu[r * ASTR + kk + lq + 4];
                af[mi][3] = Asu[(r + 8) * ASTR + kk + lq + 4];
            }
#pragma unroll
            for (int ni = 0; ni < 4; ni++) {
                int c = wn + 8 * ni + l4;
                bf[ni][0] = Bsu[(kk + lq) * BSTR + c];
                bf[ni][1] = Bsu[(kk + lq + 4) * BSTR + c];
            }
#pragma unroll
            for (int mi = 0; mi < 4; mi++)
#pragma unroll
                for (int ni = 0; ni < 4; ni++)
                    mma8(acc[mi][ni], af[mi], bf[ni]);
        }
        __syncthreads();
    }

    // epilogue
#pragma unroll
    for (int mi = 0; mi < 4; mi++) {
#pragma unroll
        for (int ni = 0; ni < 4; ni++) {
            int r = row0 + wm + 16 * mi + l4;
            int c = col0 + wn + 8 * ni + 2 * lq;
#pragma unroll
            for (int half = 0; half < 2; half++) {
                int rr = r + half * 8;
                size_t rowidx;
                if (mode == 0) rowidx = (size_t)rr;
                else { int t = rr >> 7, b = rr & 127; rowidx = (size_t)(b * TT + t); }
#pragma unroll
                for (int jj = 0; jj < 2; jj++) {
                    int cc = c + jj;
                    if (cc < N)
                        C[rowidx * ldc + cc] = acc[mi][ni][half * 2 + jj] + bias[cc];
                }
            }
        }
    }
}

// ================= fp32 tiled GEMM, reg double-buffered, optional split-K =============
// C = A[M,K]@B[K,N] (+bias).  A via lda (strided rows), B row-major ldb, C row-major ldc.
// SPLITK: blockIdx.z = ks, works on K range [ks*kchunk, min(K,+kchunk)), writes
//         partials at C + ks*M*ldc, no bias.
// Requires M%BM==0, N%BN==0, lda%4==0, kbeg%8==0; K-tail guarded (K%4==0 assumed).
template<int BM, int BN, int BK, int TM, int TN, bool SPLITK>
__global__ void gemm_f32(const float* __restrict__ A, int lda,
                         const float* __restrict__ B, int ldb,
                         const float* __restrict__ bias, float* __restrict__ C, int ldc,
                         int M, int N, int K, int kchunk)
{
    constexpr int THREADS = (BM / TM) * (BN / TN);
    constexpr int AF4 = BM * BK / 4 / THREADS;
    constexpr int BF4 = BK * BN / 4 / THREADS;
    __shared__ float As[BK][BM];
    __shared__ float Bs[BK][BN];

    const int tid = threadIdx.x;
    const int tx  = tid % (BN / TN);
    const int ty  = tid / (BN / TN);
    const int row0 = blockIdx.y * BM;
    const int col0 = blockIdx.x * BN;
    const int kbeg = SPLITK ? blockIdx.z * kchunk : 0;
    const int kend = SPLITK ? min(K, kbeg + kchunk) : K;

    float acc[TM][TN];
#pragma unroll
    for (int i = 0; i < TM; i++)
#pragma unroll
        for (int j = 0; j < TN; j++) acc[i][j] = 0.f;

    float4 pa[AF4], pb[BF4];
    auto load_regs = [&](int kt) {
#pragma unroll
        for (int i = 0; i < AF4; i++) {
            int l = tid + i * THREADS;
            int m = l / (BK / 4), kq = (l % (BK / 4)) * 4;
            int gk = kt + kq;
            pa[i] = make_float4(0.f, 0.f, 0.f, 0.f);
            if (gk < kend)
                pa[i] = *reinterpret_cast<const float4*>(A + (size_t)(row0 + m) * lda + gk);
        }
#pragma unroll
        for (int i = 0; i < BF4; i++) {
            int l = tid + i * THREADS;
            int k = l / (BN / 4), nq = (l % (BN / 4)) * 4;
            int gk = kt + k;
            pb[i] = make_float4(0.f, 0.f, 0.f, 0.f);
            if (gk < kend)
                pb[i] = *reinterpret_cast<const float4*>(B + (size_t)gk * ldb + col0 + nq);
        }
    };

    load_regs(kbeg);
    for (int kt = kbeg; kt < kend; kt += BK) {
        // STS
#pragma unroll
        for (int i = 0; i < AF4; i++) {
            int l = tid + i * THREADS;
            int m = l / (BK / 4), kq = (l % (BK / 4)) * 4;
            As[kq + 0][m] = pa[i].x; As[kq + 1][m] = pa[i].y;
            As[kq + 2][m] = pa[i].z; As[kq + 3][m] = pa[i].w;
        }
#pragma unroll
        for (int i = 0; i < BF4; i++) {
            int l = tid + i * THREADS;
            int k = l / (BN / 4), nq = (l % (BN / 4)) * 4;
            *reinterpret_cast<float4*>(&Bs[k][nq]) = pb[i];
        }
        __syncthreads();
        if (kt + BK < kend) load_regs(kt + BK);
#pragma unroll
        for (int kk = 0; kk < BK; kk++) {
            float ra[TM], rb[TN];
#pragma unroll
            for (int i = 0; i < TM; i += 4)
                *reinterpret_cast<float4*>(&ra[i]) =
                    *reinterpret_cast<const float4*>(&As[kk][ty * TM + i]);
#pragma unroll
            for (int j = 0; j < TN; j += 4)
                *reinterpret_cast<float4*>(&rb[j]) =
                    *reinterpret_cast<const float4*>(&Bs[kk][tx * TN + j]);
#pragma unroll
            for (int i = 0; i < TM; i++)
#pragma unroll
                for (int j = 0; j < TN; j++)
                    acc[i][j] = fmaf(ra[i], rb[j], acc[i][j]);
        }
        __syncthreads();
    }

    float* Cb = SPLITK ? (C + (size_t)blockIdx.z * M * ldc) : C;
#pragma unroll
    for (int i = 0; i < TM; i++) {
        int m = row0 + ty * TM + i;
#pragma unroll
        for (int j = 0; j < TN; j += 4) {
            int n = col0 + tx * TN + j;
            float4 v = make_float4(acc[i][j], acc[i][j + 1], acc[i][j + 2], acc[i][j + 3]);
            if (!SPLITK && bias) {
                v.x += bias[n]; v.y += bias[n + 1]; v.z += bias[n + 2]; v.w += bias[n + 3];
            }
            *reinterpret_cast<float4*>(Cb + (size_t)m * ldc + n) = v;
        }
    }
}

// ---------------- setup kernels ----------------
// Wcat gate-interleaved: Wcat[k][4d+g] = (k<812 ? W_ih : W_hh)[k'][g*512+d]
__global__ void wcat_kernel(const float* __restrict__ Wih, const float* __restrict__ Whh,
                            const float* __restrict__ bih, const float* __restrict__ bhh)
{
    int idx = blockIdx.x * blockDim.x + threadIdx.x;
    if (idx >= KCAT * G4) return;
    int k = idx / G4, n = idx - k * G4;
    int d = n >> 2, g = n & 3;
    int col = g * DD + d;
    float v = (k < ED + ENC) ? Wih[(size_t)k * G4 + col]
                             : Whh[(size_t)(k - ED - ENC) * G4 + col];
    g_Wcat[idx] = v;
    if (idx < G4) {
        int dd = idx >> 2, gg = idx & 3;
        int c2 = gg * DD + dd;
        g_bcat[idx] = bih[c2] + bhh[c2];
    }
}

__global__ void meanf_kernel(const float* __restrict__ feat)
{
    int idx = blockIdx.x * blockDim.x + threadIdx.x;
    if (idx >= Bc * ENC) return;
    int b = idx >> 9, d = idx & 511;
    const float* p = feat + (size_t)b * Nf * ENC + d;
    float s = 0.f;
#pragma unroll 4
    for (int n = 0; n < Nf; n++) s += p[(size_t)n * ENC];
    g_meanf[idx] = s * (1.f / (float)Nf);
}

// prefill embedding sections of xcat for all t
__global__ void embfill_kernel(const int* __restrict__ captions, const float* __restrict__ emb)
{
    int idx = blockIdx.x * blockDim.x + threadIdx.x;
    if (idx >= TT * Bc * ED) return;
    int t = idx / (Bc * ED);
    int r = idx - t * (Bc * ED);
    int b = r / ED, j = r - b * ED;
    int tok = captions[b * LL + t];
    g_xcat[((size_t)t * Bc + b) * KCAT + j] = emb[(size_t)tok * ED + j];
}

// ---------------- fused attention: scores + softmax + context ----------------
// one block per batch element, 512 threads. b_att dropped (softmax shift-invariant).
__global__ __launch_bounds__(512)
void attn_kernel(const float* __restrict__ features, const float* __restrict__ w_att,
                 float* __restrict__ alpha_out, int t)
{
    __shared__ float decp[AD];
    __shared__ float watt[AD];
    __shared__ float al[Nf];
    __shared__ float red[256];
    const int b = blockIdx.x, tid = threadIdx.x;
    decp[tid] = g_decproj[b * AD + tid];
    watt[tid] = w_att[tid];
    __syncthreads();

    const int warp = tid >> 5, lane = tid & 31;
    for (int n = warp; n < Nf; n += 16) {
        const float* fp = g_featproj + ((size_t)b * Nf + n) * AD;
        float s = 0.f;
#pragma unroll 4
        for (int a = lane; a < AD; a += 32)
            s += tanhf(fp[a] + decp[a]) * watt[a];
#pragma unroll
        for (int o = 16; o; o >>= 1) s += __shfl_xor_sync(0xFFFFFFFFu, s, o);
        if (lane == 0) al[n] = s;
    }
    __syncthreads();

    if (tid < 256) red[tid] = (tid < Nf) ? al[tid] : -1e30f;
    __syncthreads();
    for (int s = 128; s; s >>= 1) { if (tid < s) red[tid] = fmaxf(red[tid], red[tid + s]); __syncthreads(); }
    float mx = red[0];
    __syncthreads();
    float e = (tid < Nf) ? expf(al[tid] - mx) : 0.f;
    if (tid < 256) red[tid] = e;
    __syncthreads();
    for (int s = 128; s; s >>= 1) { if (tid < s) red[tid] += red[tid + s]; __syncthreads(); }
    float inv = 1.f / red[0];
    if (tid < Nf) {
        float a = e * inv;
        al[tid] = a;
        if (alpha_out) alpha_out[(size_t)(b * TT + t) * Nf + tid] = a;
    }
    __syncthreads();

    // context[d] = sum_n alpha[n]*features[b,n,d] -> xcat[t][b][ED+d]
    const float* fb = features + (size_t)b * Nf * ENC;
    float s = 0.f;
#pragma unroll 4
    for (int n = 0; n < Nf; n++) s += al[n] * fb[(size_t)n * ENC + tid];
    g_xcat[((size_t)t * Bc + b) * KCAT + ED + tid] = s;
}

// ---------------- split-K reduce + LSTM (gate-interleaved float4 per unit) ----------------
__global__ void lstm_reduce(int t)
{
    int idx = blockIdx.x * blockDim.x + threadIdx.x;
    if (idx >= Bc * DD) return;
    int b = idx >> 9, d = idx & 511;
    float4 g = reinterpret_cast<const float4*>(g_bcat)[d];
    const float4* gp = reinterpret_cast<const float4*>(g_gpart);
#pragma unroll
    for (int ks = 0; ks < KS; ks++) {
        float4 p = gp[((size_t)(ks * Bc + b) * G4 >> 2) + d];
        g.x += p.x; g.y += p.y; g.z += p.z; g.w += p.w;
    }
    float si = 1.f / (1.f + expf(-g.x));
    float sf = 1.f / (1.f + expf(-g.y));
    float so = 1.f / (1.f + expf(-g.w));
    float cn = sf * g_c[idx] + si * tanhf(g.z);
    float hn = so * tanhf(cn);
    g_c[idx] = cn;
    g_Hall[(size_t)t * Bc * DD + idx] = hn;
    if (t + 1 < TT)
        g_xcat[((size_t)(t + 1) * Bc + b) * KCAT + ED + ENC + d] = hn;
}

// ---------------- host launcher ----------------
extern "C" void kernel_launch(void* const* d_in, const int* in_sizes, int n_in,
                              void* d_out, int out_size)
{
    const float* features = (const float*)d_in[0];
    const int*   captions = (const int*)  d_in[1];
    const float* embedding= (const float*)d_in[2];
    const float* W_enc    = (const float*)d_in[3];
    const float* b_enc    = (const float*)d_in[4];
    const float* W_dec    = (const float*)d_in[5];
    // d_in[6] b_dec: additive const inside tanh argument? No — b_dec shifts dec_proj,
    // which DOES change tanh input. Must keep it. (handled below via bias in GEMM)
    const float* b_dec    = (const float*)d_in[6];
    const float* w_att    = (const float*)d_in[7];
    // d_in[8] b_att: pure softmax shift — dropped.
    const float* Wi_h     = (const float*)d_in[9];
    const float* bi_h     = (const float*)d_in[10];
    const float* Wi_c     = (const float*)d_in[11];
    const float* bi_c     = (const float*)d_in[12];
    const float* W_ih     = (const float*)d_in[13];
    const float* b_ih     = (const float*)d_in[14];
    const float* W_hh     = (const float*)d_in[15];
    const float* b_hh     = (const float*)d_in[16];
    const float* W_out    = (const float*)d_in[17];
    const float* b_out    = (const float*)d_in[18];

    float* out = (float*)d_out;
    const size_t PRED_SZ = (size_t)Bc * TT * VV;
    float* alpha_out = ((size_t)out_size >= PRED_SZ + (size_t)Bc * TT * Nf)
                           ? (out + PRED_SZ) : nullptr;

    static float *p_featproj = nullptr, *p_Wcat, *p_bcat, *p_meanf, *p_c,
                 *p_decproj, *p_xcat, *p_gpart, *p_Hall;
    if (!p_featproj) {
        cudaGetSymbolAddress((void**)&p_featproj, g_featproj);
        cudaGetSymbolAddress((void**)&p_Wcat,     g_Wcat);
        cudaGetSymbolAddress((void**)&p_bcat,     g_bcat);
        cudaGetSymbolAddress((void**)&p_meanf,    g_meanf);
        cudaGetSymbolAddress((void**)&p_c,        g_c);
        cudaGetSymbolAddress((void**)&p_decproj,  g_decproj);
        cudaGetSymbolAddress((void**)&p_xcat,     g_xcat);
        cudaGetSymbolAddress((void**)&p_gpart,    g_gpart);
        cudaGetSymbolAddress((void**)&p_Hall,     g_Hall);
    }

    // ---- setup ----
    wcat_kernel<<<(KCAT * G4 + 255) / 256, 256>>>(W_ih, W_hh, b_ih, b_hh);
    meanf_kernel<<<(Bc * ENC + 255) / 256, 256>>>(features);
    embfill_kernel<<<(TT * Bc * ED + 255) / 256, 256>>>(captions, embedding);

    // h0 -> xcat[0].h ; c0 -> g_c   (fp32 GEMM, 32x64 tiles, TM=TN=4)
    {
        dim3 grid(DD / 64, Bc / 32);
        gemm_f32<32, 64, 32, 4, 4, false><<<grid, 128>>>(
            p_meanf, ENC, Wi_h, DD, bi_h, p_xcat + ED + ENC, KCAT, Bc, DD, ENC, ENC);
        gemm_f32<32, 64, 32, 4, 4, false><<<grid, 128>>>(
            p_meanf, ENC, Wi_c, DD, bi_c, p_c, DD, Bc, DD, ENC, ENC);
    }

    // feat_proj = features @ W_enc + b_enc  (tf32 tensor cores)
    {
        dim3 grid(AD / 128, (Bc * Nf) / 128);   // (4, 196)
        gemm_tf32<<<grid, 256>>>(features, ENC, W_enc, AD, b_enc,
                                 p_featproj, AD, Bc * Nf, AD, ENC, 0);
    }

    // ---- serial step loop ----
    for (int t = 0; t < TT; t++) {
        // dec_proj = h_t @ W_dec + b_dec   (A = xcat[t].h strided rows)
        {
            dim3 grid(AD / 64, Bc / 32);
            gemm_f32<32, 64, 32, 4, 4, false><<<grid, 128>>>(
                p_xcat + (size_t)t * Bc * KCAT + ED + ENC, KCAT,
                W_dec, AD, b_dec, p_decproj, AD, Bc, AD, DD, DD);
        }
        attn_kernel<<<Bc, 512>>>(features, w_att, alpha_out, t);
        // gates partials = xcat[t] @ Wcat   (split-K=8, 64x128 tiles, 8x8 regs)
        {
            dim3 grid(G4 / 128, Bc / 64, KS);   // (16, 2, 8)
            gemm_f32<64, 128, 32, 8, 8, true><<<grid, 128>>>(
                p_xcat + (size_t)t * Bc * KCAT, KCAT,
                p_Wcat, G4, nullptr, p_gpart, G4, Bc, G4, KCAT, KCHUNK);
        }
        lstm_reduce<<<(Bc * DD + 255) / 256, 256>>>(t);
    }

    // ---- preds = Hall @ W_out + b_out, remap [t*128+b] -> out[(b*TT+t)*V] ----
    {
        dim3 grid((VV + 127) / 128, (TT * Bc) / 128);   // (79, 24)
        gemm_tf32<<<grid, 256>>>(p_Hall, DD, W_out, VV, b_out,
                                 out, VV, TT * Bc, VV, DD, 1);
    }
}

// round 4
// speedup vs baseline: 2.2138x; 1.3303x over previous
#include <cuda_runtime.h>
#include <cstdint>

// ---------------- problem dims ----------------
constexpr int Bc   = 128;     // batch
constexpr int Nf   = 196;     // spatial features
constexpr int ENC  = 512;
constexpr int AD   = 512;     // attention dim
constexpr int DD   = 512;     // decoder dim
constexpr int ED   = 300;     // embed dim
constexpr int VV   = 10000;   // vocab
constexpr int LL   = 25;
constexpr int TT   = 24;      // L-1
constexpr int KCAT = ED + ENC + DD;   // 1324
constexpr int G4   = 4 * DD;          // 2048
constexpr int KS   = 8;               // split-K for gates GEMM
constexpr int GCHUNK = 168;           // 1324/8 rounded (mult of 4)
constexpr int DPS  = 4;               // split-K for dec_proj
constexpr int DPCHUNK = 128;

// ---------------- device scratch (static; no runtime alloc) ----------------
__device__ float g_featproj[Bc * Nf * AD];        // 51.4 MB
__device__ float g_Wcat[KCAT * G4];               // 10.9 MB (gate-interleaved col=4d+g)
__device__ float g_bcat[G4];
__device__ float g_meanf[Bc * ENC];
__device__ float g_c[Bc * DD];
__device__ float g_dppart[DPS * Bc * AD];         // dec_proj split-K partials (1 MB)
__device__ float g_xcat[TT * Bc * KCAT];          // 16.3 MB  [t][b][emb|ctx|h]
__device__ float g_gpart[KS * Bc * G4];           // 8 MB gates split-K partials
__device__ float g_Hall[TT * Bc * DD];            // 6.3 MB

// ================= TF32 tensor-core GEMM (unified) =================
// C = A[M,K] @ B[K,N] (+ bias).  128x128x32 CTA tile, 256 thr, 8 warps (2x4),
// warp tile 64x32, mma.m16n8k8.tf32, RNA conversion at STS, reg double-buffered LDG.
// MODE 0: C[m*ldc+n] + bias
// MODE 1: m=t*128+b -> C[(b*TT+t)*ldc+n] + bias  (preds remap)
// MODE 2: split-K partial: K range [z*kchunk, min(K, +kchunk)), C += z*M*ldc, no bias
// Requires: M%128==0, K%4==0, kchunk%4==0, lda%4==0, ldb%4==0, N%4==0.
__device__ __forceinline__ uint32_t f2tf(float x) {
    uint32_t r; asm("cvt.rna.tf32.f32 %0, %1;" : "=r"(r) : "f"(x)); return r;
}
__device__ __forceinline__ void mma8(float* c, const uint32_t* a, const uint32_t* b) {
    asm volatile("mma.sync.aligned.m16n8k8.row.col.f32.tf32.tf32.f32 "
                 "{%0,%1,%2,%3},{%4,%5,%6,%7},{%8,%9},{%0,%1,%2,%3};"
                 : "+f"(c[0]), "+f"(c[1]), "+f"(c[2]), "+f"(c[3])
                 : "r"(a[0]), "r"(a[1]), "r"(a[2]), "r"(a[3]), "r"(b[0]), "r"(b[1]));
}

template<int MODE>
__global__ __launch_bounds__(256)
void gemm_tc(const float* __restrict__ A, int lda,
             const float* __restrict__ B, int ldb,
             const float* __restrict__ bias, float* __restrict__ C, int ldc,
             int M, int N, int K, int kchunk)
{
    constexpr int ASTR = 36;
    constexpr int BSTR = 136;
    __shared__ float As[128 * ASTR];   // [m][k]
    __shared__ float Bs[32 * BSTR];    // [k][n]

    const int tid  = threadIdx.x;
    const int lane = tid & 31, warp = tid >> 5;
    const int wm = (warp >> 2) * 64;
    const int wn = (warp & 3) * 32;
    const int l4 = lane >> 2, lq = lane & 3;
    const int row0 = blockIdx.y * 128;
    const int col0 = blockIdx.x * 128;
    const int kbeg = (MODE == 2) ? blockIdx.z * kchunk : 0;
    const int kend = (MODE == 2) ? min(K, kbeg + kchunk) : K;

    float acc[4][4][4];
#pragma unroll
    for (int i = 0; i < 4; i++)
#pragma unroll
        for (int j = 0; j < 4; j++)
#pragma unroll
            for (int q = 0; q < 4; q++) acc[i][j][q] = 0.f;

    const uint32_t* Asu = reinterpret_cast<const uint32_t*>(As);
    const uint32_t* Bsu = reinterpret_cast<const uint32_t*>(Bs);

    float4 pa[4], pb[4];
    auto ldA = [&](int kt) {
#pragma unroll
        for (int i = 0; i < 4; i++) {
            int l = tid + i * 256;
            int m = l >> 3, kq = (l & 7) << 2;
            int gk = kt + kq;
            pa[i] = make_float4(0.f, 0.f, 0.f, 0.f);
            if (gk < kend)
                pa[i] = *reinterpret_cast<const float4*>(A + (size_t)(row0 + m) * lda + gk);
        }
    };
    auto ldB = [&](int kt) {
#pragma unroll
        for (int i = 0; i < 4; i++) {
            int l = tid + i * 256;
            int k = l >> 5, nq = (l & 31) << 2;
            int gk = kt + k, gn = col0 + nq;
            pb[i] = make_float4(0.f, 0.f, 0.f, 0.f);
            if (gk < kend && gn < N)
                pb[i] = *reinterpret_cast<const float4*>(B + (size_t)gk * ldb + gn);
        }
    };

    ldA(kbeg); ldB(kbeg);
    for (int kt = kbeg; kt < kend; kt += 32) {
        // STS with RNA conversion
#pragma unroll
        for (int i = 0; i < 4; i++) {
            int l = tid + i * 256;
            int m = l >> 3, kq = (l & 7) << 2;
            uint4 u = make_uint4(f2tf(pa[i].x), f2tf(pa[i].y), f2tf(pa[i].z), f2tf(pa[i].w));
            *reinterpret_cast<uint4*>(As + m * ASTR + kq) = u;
        }
#pragma unroll
        for (int i = 0; i < 4; i++) {
            int l = tid + i * 256;
            int k = l >> 5, nq = (l & 31) << 2;
            uint4 u = make_uint4(f2tf(pb[i].x), f2tf(pb[i].y), f2tf(pb[i].z), f2tf(pb[i].w));
            *reinterpret_cast<uint4*>(Bs + k * BSTR + nq) = u;
        }
        __syncthreads();
        if (kt + 32 < kend) { ldA(kt + 32); ldB(kt + 32); }  // prefetch next tile
#pragma unroll
        for (int kk = 0; kk < 32; kk += 8) {
            uint32_t af[4][4], bf[4][2];
#pragma unroll
            for (int mi = 0; mi < 4; mi++) {
                int r = wm + 16 * mi + l4;
                af[mi][0] = Asu[r * ASTR + kk + lq];
                af[mi][1] = Asu[(r + 8) * ASTR + kk + lq];
                af[mi][2] = Asu[r * ASTR + kk + lq + 4];
                af[mi][3] = Asu[(r + 8) * ASTR + kk + lq + 4];
            }
#pragma unroll
            for (int ni = 0; ni < 4; ni++) {
                int c = wn + 8 * ni + l4;
                bf[ni][0] = Bsu[(kk + lq) * BSTR + c];
                bf[ni][1] = Bsu[(kk + lq + 4) * BSTR + c];
            }
#pragma unroll
            for (int mi = 0; mi < 4; mi++)
#pragma unroll
                for (int ni = 0; ni < 4; ni++)
                    mma8(acc[mi][ni], af[mi], bf[ni]);
        }
        __syncthreads();
    }

    float* Cb = (MODE == 2) ? (C + (size_t)blockIdx.z * M * ldc) : C;
#pragma unroll
    for (int mi = 0; mi < 4; mi++) {
#pragma unroll
        for (int ni = 0; ni < 4; ni++) {
            int r = row0 + wm + 16 * mi + l4;
            int c = col0 + wn + 8 * ni + 2 * lq;
#pragma unroll
            for (int half = 0; half < 2; half++) {
                int rr = r + half * 8;
                size_t rowidx;
                if (MODE == 1) { int t = rr >> 7, b = rr & 127; rowidx = (size_t)(b * TT + t); }
                else rowidx = (size_t)rr;
#pragma unroll
                for (int jj = 0; jj < 2; jj++) {
                    int cc = c + jj;
                    if (cc < N) {
                        float v = acc[mi][ni][half * 2 + jj];
                        if (MODE != 2) v += bias[cc];
                        Cb[rowidx * ldc + cc] = v;
                    }
                }
            }
        }
    }
}

// ================= fp32 GEMM (h0/c0 only; small, run once) =================
template<int BM, int BN, int BK, int TM, int TN>
__global__ void gemm_f32(const float* __restrict__ A, int lda,
                         const float* __restrict__ B, int ldb,
                         const float* __restrict__ bias, float* __restrict__ C, int ldc,
                         int M, int N, int K)
{
    constexpr int THREADS = (BM / TM) * (BN / TN);
    constexpr int AF4 = BM * BK / 4 / THREADS;
    constexpr int BF4 = BK * BN / 4 / THREADS;
    __shared__ float As[BK][BM];
    __shared__ float Bs[BK][BN];
    const int tid = threadIdx.x;
    const int tx = tid % (BN / TN), ty = tid / (BN / TN);
    const int row0 = blockIdx.y * BM, col0 = blockIdx.x * BN;

    float acc[TM][TN];
#pragma unroll
    for (int i = 0; i < TM; i++)
#pragma unroll
        for (int j = 0; j < TN; j++) acc[i][j] = 0.f;

    float4 pa[AF4], pb[BF4];
    auto load_regs = [&](int kt) {
#pragma unroll
        for (int i = 0; i < AF4; i++) {
            int l = tid + i * THREADS;
            int m = l / (BK / 4), kq = (l % (BK / 4)) * 4;
            pa[i] = *reinterpret_cast<const float4*>(A + (size_t)(row0 + m) * lda + kt + kq);
        }
#pragma unroll
        for (int i = 0; i < BF4; i++) {
            int l = tid + i * THREADS;
            int k = l / (BN / 4), nq = (l % (BN / 4)) * 4;
            pb[i] = *reinterpret_cast<const float4*>(B + (size_t)(kt + k) * ldb + col0 + nq);
        }
    };
    load_regs(0);
    for (int kt = 0; kt < K; kt += BK) {
#pragma unroll
        for (int i = 0; i < AF4; i++) {
            int l = tid + i * THREADS;
            int m = l / (BK / 4), kq = (l % (BK / 4)) * 4;
            As[kq + 0][m] = pa[i].x; As[kq + 1][m] = pa[i].y;
            As[kq + 2][m] = pa[i].z; As[kq + 3][m] = pa[i].w;
        }
#pragma unroll
        for (int i = 0; i < BF4; i++) {
            int l = tid + i * THREADS;
            int k = l / (BN / 4), nq = (l % (BN / 4)) * 4;
            *reinterpret_cast<float4*>(&Bs[k][nq]) = pb[i];
        }
        __syncthreads();
        if (kt + BK < K) load_regs(kt + BK);
#pragma unroll
        for (int kk = 0; kk < BK; kk++) {
            float ra[TM], rb[TN];
#pragma unroll
            for (int i = 0; i < TM; i += 4)
                *reinterpret_cast<float4*>(&ra[i]) =
                    *reinterpret_cast<const float4*>(&As[kk][ty * TM + i]);
#pragma unroll
            for (int j = 0; j < TN; j += 4)
                *reinterpret_cast<float4*>(&rb[j]) =
                    *reinterpret_cast<const float4*>(&Bs[kk][tx * TN + j]);
#pragma unroll
            for (int i = 0; i < TM; i++)
#pragma unroll
                for (int j = 0; j < TN; j++)
                    acc[i][j] = fmaf(ra[i], rb[j], acc[i][j]);
        }
        __syncthreads();
    }
#pragma unroll
    for (int i = 0; i < TM; i++) {
        int m = row0 + ty * TM + i;
#pragma unroll
        for (int j = 0; j < TN; j += 4) {
            int n = col0 + tx * TN + j;
            float4 v = make_float4(acc[i][j] + bias[n], acc[i][j + 1] + bias[n + 1],
                                   acc[i][j + 2] + bias[n + 2], acc[i][j + 3] + bias[n + 3]);
            *reinterpret_cast<float4*>(C + (size_t)m * ldc + n) = v;
        }
    }
}

// ---------------- setup kernels ----------------
__global__ void wcat_kernel(const float* __restrict__ Wih, const float* __restrict__ Whh,
                            const float* __restrict__ bih, const float* __restrict__ bhh)
{
    int idx = blockIdx.x * blockDim.x + threadIdx.x;
    if (idx >= KCAT * G4) return;
    int k = idx / G4, n = idx - k * G4;
    int d = n >> 2, g = n & 3;
    int col = g * DD + d;
    float v = (k < ED + ENC) ? Wih[(size_t)k * G4 + col]
                             : Whh[(size_t)(k - ED - ENC) * G4 + col];
    g_Wcat[idx] = v;
    if (idx < G4) {
        int dd = idx >> 2, gg = idx & 3;
        int c2 = gg * DD + dd;
        g_bcat[idx] = bih[c2] + bhh[c2];
    }
}

__global__ void meanf_kernel(const float* __restrict__ feat)
{
    int idx = blockIdx.x * blockDim.x + threadIdx.x;
    if (idx >= Bc * ENC) return;
    int b = idx >> 9, d = idx & 511;
    const float* p = feat + (size_t)b * Nf * ENC + d;
    float s = 0.f;
#pragma unroll 4
    for (int n = 0; n < Nf; n++) s += p[(size_t)n * ENC];
    g_meanf[idx] = s * (1.f / (float)Nf);
}

__global__ void embfill_kernel(const int* __restrict__ captions, const float* __restrict__ emb)
{
    int idx = blockIdx.x * blockDim.x + threadIdx.x;
    if (idx >= TT * Bc * ED) return;
    int t = idx / (Bc * ED);
    int r = idx - t * (Bc * ED);
    int b = r / ED, j = r - b * ED;
    int tok = captions[b * LL + t];
    g_xcat[((size_t)t * Bc + b) * KCAT + j] = emb[(size_t)tok * ED + j];
}

// ---------------- fused attention (incl. dec_proj split-K reduce) ----------------
__global__ __launch_bounds__(512)
void attn_kernel(const float* __restrict__ features, const float* __restrict__ w_att,
                 const float* __restrict__ b_dec, float* __restrict__ alpha_out, int t)
{
    __shared__ float decp[AD];
    __shared__ float watt[AD];
    __shared__ float al[Nf];
    __shared__ float red[256];
    const int b = blockIdx.x, tid = threadIdx.x;
    // reduce dec_proj split-K partials + b_dec
    {
        float s = b_dec[tid];
#pragma unroll
        for (int z = 0; z < DPS; z++)
            s += g_dppart[((size_t)z * Bc + b) * AD + tid];
        decp[tid] = s;
    }
    watt[tid] = w_att[tid];
    __syncthreads();

    const int warp = tid >> 5, lane = tid & 31;
    for (int n = warp; n < Nf; n += 16) {
        const float* fp = g_featproj + ((size_t)b * Nf + n) * AD;
        float s = 0.f;
#pragma unroll 4
        for (int a = lane; a < AD; a += 32)
            s += tanhf(fp[a] + decp[a]) * watt[a];
#pragma unroll
        for (int o = 16; o; o >>= 1) s += __shfl_xor_sync(0xFFFFFFFFu, s, o);
        if (lane == 0) al[n] = s;
    }
    __syncthreads();

    if (tid < 256) red[tid] = (tid < Nf) ? al[tid] : -1e30f;
    __syncthreads();
    for (int s = 128; s; s >>= 1) { if (tid < s) red[tid] = fmaxf(red[tid], red[tid + s]); __syncthreads(); }
    float mx = red[0];
    __syncthreads();
    float e = (tid < Nf) ? expf(al[tid] - mx) : 0.f;
    if (tid < 256) red[tid] = e;
    __syncthreads();
    for (int s = 128; s; s >>= 1) { if (tid < s) red[tid] += red[tid + s]; __syncthreads(); }
    float inv = 1.f / red[0];
    if (tid < Nf) {
        float a = e * inv;
        al[tid] = a;
        if (alpha_out) alpha_out[(size_t)(b * TT + t) * Nf + tid] = a;
    }
    __syncthreads();

    const float* fb = features + (size_t)b * Nf * ENC;
    float s = 0.f;
#pragma unroll 4
    for (int n = 0; n < Nf; n++) s += al[n] * fb[(size_t)n * ENC + tid];
    g_xcat[((size_t)t * Bc + b) * KCAT + ED + tid] = s;
}

// ---------------- split-K reduce + LSTM pointwise ----------------
__global__ void lstm_reduce(int t)
{
    int idx = blockIdx.x * blockDim.x + threadIdx.x;
    if (idx >= Bc * DD) return;
    int b = idx >> 9, d = idx & 511;
    float4 g = reinterpret_cast<const float4*>(g_bcat)[d];
    const float4* gp = reinterpret_cast<const float4*>(g_gpart);
#pragma unroll
    for (int ks = 0; ks < KS; ks++) {
        float4 p = gp[((size_t)(ks * Bc + b) * G4 >> 2) + d];
        g.x += p.x; g.y += p.y; g.z += p.z; g.w += p.w;
    }
    float si = 1.f / (1.f + expf(-g.x));
    float sf = 1.f / (1.f + expf(-g.y));
    float so = 1.f / (1.f + expf(-g.w));
    float cn = sf * g_c[idx] + si * tanhf(g.z);
    float hn = so * tanhf(cn);
    g_c[idx] = cn;
    g_Hall[(size_t)t * Bc * DD + idx] = hn;
    if (t + 1 < TT)
        g_xcat[((size_t)(t + 1) * Bc + b) * KCAT + ED + ENC + d] = hn;
}

// ---------------- host launcher ----------------
extern "C" void kernel_launch(void* const* d_in, const int* in_sizes, int n_in,
                              void* d_out, int out_size)
{
    const float* features = (const float*)d_in[0];
    const int*   captions = (const int*)  d_in[1];
    const float* embedding= (const float*)d_in[2];
    const float* W_enc    = (const float*)d_in[3];
    const float* b_enc    = (const float*)d_in[4];
    const float* W_dec    = (const float*)d_in[5];
    const float* b_dec    = (const float*)d_in[6];
    const float* w_att    = (const float*)d_in[7];
    // d_in[8] b_att: softmax shift-invariant — dropped
    const float* Wi_h     = (const float*)d_in[9];
    const float* bi_h     = (const float*)d_in[10];
    const float* Wi_c     = (const float*)d_in[11];
    const float* bi_c     = (const float*)d_in[12];
    const float* W_ih     = (const float*)d_in[13];
    const float* b_ih     = (const float*)d_in[14];
    const float* W_hh     = (const float*)d_in[15];
    const float* b_hh     = (const float*)d_in[16];
    const float* W_out    = (const float*)d_in[17];
    const float* b_out    = (const float*)d_in[18];

    float* out = (float*)d_out;
    const size_t PRED_SZ = (size_t)Bc * TT * VV;
    float* alpha_out = ((size_t)out_size >= PRED_SZ + (size_t)Bc * TT * Nf)
                           ? (out + PRED_SZ) : nullptr;

    static float *p_featproj = nullptr, *p_Wcat, *p_meanf, *p_c,
                 *p_dppart, *p_xcat, *p_gpart, *p_Hall;
    if (!p_featproj) {
        cudaGetSymbolAddress((void**)&p_featproj, g_featproj);
        cudaGetSymbolAddress((void**)&p_Wcat,     g_Wcat);
        cudaGetSymbolAddress((void**)&p_meanf,    g_meanf);
        cudaGetSymbolAddress((void**)&p_c,        g_c);
        cudaGetSymbolAddress((void**)&p_dppart,   g_dppart);
        cudaGetSymbolAddress((void**)&p_xcat,     g_xcat);
        cudaGetSymbolAddress((void**)&p_gpart,    g_gpart);
        cudaGetSymbolAddress((void**)&p_Hall,     g_Hall);
    }

    // ---- setup ----
    wcat_kernel<<<(KCAT * G4 + 255) / 256, 256>>>(W_ih, W_hh, b_ih, b_hh);
    meanf_kernel<<<(Bc * ENC + 255) / 256, 256>>>(features);
    embfill_kernel<<<(TT * Bc * ED + 255) / 256, 256>>>(captions, embedding);

    // h0 -> xcat[0].h ; c0 -> g_c  (fp32, exact, run once)
    {
        dim3 grid(DD / 64, Bc / 32);
        gemm_f32<32, 64, 32, 4, 4><<<grid, 128>>>(
            p_meanf, ENC, Wi_h, DD, bi_h, p_xcat + ED + ENC, KCAT, Bc, DD, ENC);
        gemm_f32<32, 64, 32, 4, 4><<<grid, 128>>>(
            p_meanf, ENC, Wi_c, DD, bi_c, p_c, DD, Bc, DD, ENC);
    }

    // feat_proj = features @ W_enc + b_enc
    {
        dim3 grid(AD / 128, (Bc * Nf) / 128);   // (4, 196)
        gemm_tc<0><<<grid, 256>>>(features, ENC, W_enc, AD, b_enc,
                                  p_featproj, AD, Bc * Nf, AD, ENC, 0);
    }

    // ---- serial step loop ----
    for (int t = 0; t < TT; t++) {
        // dec_proj partials = h_t @ W_dec  (tf32 split-K=4; reduced in attn_kernel)
        {
            dim3 grid(AD / 128, 1, DPS);        // (4,1,4)
            gemm_tc<2><<<grid, 256>>>(
                p_xcat + (size_t)t * Bc * KCAT + ED + ENC, KCAT,
                W_dec, AD, nullptr, p_dppart, AD, Bc, AD, DD, DPCHUNK);
        }
        attn_kernel<<<Bc, 512>>>(features, w_att, b_dec, alpha_out, t);
        // gates partials = xcat[t] @ Wcat  (tf32 split-K=8)
        {
            dim3 grid(G4 / 128, 1, KS);         // (16,1,8)
            gemm_tc<2><<<grid, 256>>>(
                p_xcat + (size_t)t * Bc * KCAT, KCAT,
                p_Wcat, G4, nullptr, p_gpart, G4, Bc, G4, KCAT, GCHUNK);
        }
        lstm_reduce<<<(Bc * DD + 255) / 256, 256>>>(t);
    }

    // ---- preds = Hall @ W_out + b_out, remap [t*128+b] -> out[(b*TT+t)*V] ----
    {
        dim3 grid((VV + 127) / 128, (TT * Bc) / 128);   // (79, 24)
        gemm_tc<1><<<grid, 256>>>(p_Hall, DD, W_out, VV, b_out,
                                  out, VV, TT * Bc, VV, DD, 0);
    }
}